// round 2
// baseline (speedup 1.0000x reference)
#include <cuda_runtime.h>
#include <cuda_bf16.h>

// Problem: logits[i] = sum_{(i,j) in E} Wt[j] + b ; out = log_softmax(logits, axis=1)
// N=100000, E=3200000, C=64.
// NOTE: edge_index is int32 (JAX default x64-disabled downcasts jnp.int64 -> int32).
// Strategy:
//   K1: init d_out[n][c] = b[c]
//   K2: 16 threads/edge, float4 gather from Wt (L2-resident, 25.6MB),
//       red.global.add.v4.f32 scatter into d_out.
//   K3: one warp per row log_softmax in-place (2 cols per lane).

#define C 64

__global__ void init_kernel(float* __restrict__ out, const float* __restrict__ b, int total) {
    int i = blockIdx.x * blockDim.x + threadIdx.x;
    if (i < total) {
        out[i] = __ldg(&b[i & (C - 1)]);
    }
}

__global__ void scatter_kernel(const int* __restrict__ ei,
                               const float* __restrict__ Wt,
                               float* __restrict__ out,
                               int E) {
    int gtid = blockIdx.x * blockDim.x + threadIdx.x;
    int e = gtid >> 4;           // 16 threads per edge
    int lane = threadIdx.x & 15; // float4 slot 0..15 (16*16B = 256B = one row)
    if (e >= E) return;

    // all 16 lanes read the same addresses -> L1 broadcast, 1 transaction each
    int row = __ldg(&ei[e]);
    int col = __ldg(&ei[E + e]);

    const float4* src = reinterpret_cast<const float4*>(Wt + (long long)col * C);
    float4 v = __ldg(&src[lane]);

    float* dst = out + (long long)row * C + lane * 4;
    asm volatile("red.global.add.v4.f32 [%0], {%1, %2, %3, %4};"
                 :: "l"(dst), "f"(v.x), "f"(v.y), "f"(v.z), "f"(v.w)
                 : "memory");
}

__global__ void softmax_kernel(float* __restrict__ out, int N) {
    int warp = (blockIdx.x * blockDim.x + threadIdx.x) >> 5;
    int lane = threadIdx.x & 31;
    if (warp >= N) return;

    float* rowp = out + (long long)warp * C;
    float v0 = rowp[lane];
    float v1 = rowp[lane + 32];

    // max reduce
    float m = fmaxf(v0, v1);
    #pragma unroll
    for (int off = 16; off > 0; off >>= 1)
        m = fmaxf(m, __shfl_xor_sync(0xffffffffu, m, off));

    // sum of exp
    float s = __expf(v0 - m) + __expf(v1 - m);
    #pragma unroll
    for (int off = 16; off > 0; off >>= 1)
        s += __shfl_xor_sync(0xffffffffu, s, off);

    float lse = m + logf(s);
    rowp[lane]      = v0 - lse;
    rowp[lane + 32] = v1 - lse;
}

extern "C" void kernel_launch(void* const* d_in, const int* in_sizes, int n_in,
                              void* d_out, int out_size) {
    const int*   ei = (const int*)d_in[0];   // [2, E] int32
    const float* Wt = (const float*)d_in[1]; // [N, C]
    const float* b  = (const float*)d_in[2]; // [C]
    float* out = (float*)d_out;              // [N, C]

    int E = in_sizes[0] / 2;
    int N = in_sizes[1] / C;
    int total = N * C;

    // K1: init with bias
    {
        int threads = 256;
        int blocks = (total + threads - 1) / threads;
        init_kernel<<<blocks, threads>>>(out, b, total);
    }
    // K2: edge scatter
    {
        int threads = 256;
        long long work = (long long)E * 16;
        int blocks = (int)((work + threads - 1) / threads);
        scatter_kernel<<<blocks, threads>>>(ei, Wt, out, E);
    }
    // K3: log_softmax per row
    {
        int threads = 256;                 // 8 warps/block
        int blocks = (N + 7) / 8;
        softmax_kernel<<<blocks, threads>>>(out, N);
    }
}

// round 3
// speedup vs baseline: 1.0067x; 1.0067x over previous
#include <cuda_runtime.h>
#include <cuda_bf16.h>

// Problem: logits[i] = sum_{(i,j) in E} Wt[j] + b ; out = log_softmax(logits, axis=1)
// N=100000, E=3200000, C=64.
// NOTE: edge_index is int32 (JAX default x64-disabled downcasts jnp.int64 -> int32).
// Strategy:
//   K1: init d_out[n][c] = b[c]
//   K2: 16 threads/edge, float4 gather from Wt (L2-resident, 25.6MB),
//       red.global.add.v4.f32 scatter into d_out.
//   K3: one warp per row log_softmax in-place (2 cols per lane).

#define C 64

__global__ void init_kernel(float* __restrict__ out, const float* __restrict__ b, int total) {
    int i = blockIdx.x * blockDim.x + threadIdx.x;
    if (i < total) {
        out[i] = __ldg(&b[i & (C - 1)]);
    }
}

__global__ void scatter_kernel(const int* __restrict__ ei,
                               const float* __restrict__ Wt,
                               float* __restrict__ out,
                               int E) {
    int gtid = blockIdx.x * blockDim.x + threadIdx.x;
    int e = gtid >> 4;           // 16 threads per edge
    int lane = threadIdx.x & 15; // float4 slot 0..15 (16*16B = 256B = one row)
    if (e >= E) return;

    // all 16 lanes read the same addresses -> L1 broadcast, 1 transaction each
    int row = __ldg(&ei[e]);
    int col = __ldg(&ei[E + e]);

    const float4* src = reinterpret_cast<const float4*>(Wt + (long long)col * C);
    float4 v = __ldg(&src[lane]);

    float* dst = out + (long long)row * C + lane * 4;
    asm volatile("red.global.add.v4.f32 [%0], {%1, %2, %3, %4};"
                 :: "l"(dst), "f"(v.x), "f"(v.y), "f"(v.z), "f"(v.w)
                 : "memory");
}

__global__ void softmax_kernel(float* __restrict__ out, int N) {
    int warp = (blockIdx.x * blockDim.x + threadIdx.x) >> 5;
    int lane = threadIdx.x & 31;
    if (warp >= N) return;

    float* rowp = out + (long long)warp * C;
    float v0 = rowp[lane];
    float v1 = rowp[lane + 32];

    // max reduce
    float m = fmaxf(v0, v1);
    #pragma unroll
    for (int off = 16; off > 0; off >>= 1)
        m = fmaxf(m, __shfl_xor_sync(0xffffffffu, m, off));

    // sum of exp
    float s = __expf(v0 - m) + __expf(v1 - m);
    #pragma unroll
    for (int off = 16; off > 0; off >>= 1)
        s += __shfl_xor_sync(0xffffffffu, s, off);

    float lse = m + logf(s);
    rowp[lane]      = v0 - lse;
    rowp[lane + 32] = v1 - lse;
}

extern "C" void kernel_launch(void* const* d_in, const int* in_sizes, int n_in,
                              void* d_out, int out_size) {
    const int*   ei = (const int*)d_in[0];   // [2, E] int32
    const float* Wt = (const float*)d_in[1]; // [N, C]
    const float* b  = (const float*)d_in[2]; // [C]
    float* out = (float*)d_out;              // [N, C]

    int E = in_sizes[0] / 2;
    int N = in_sizes[1] / C;
    int total = N * C;

    // K1: init with bias
    {
        int threads = 256;
        int blocks = (total + threads - 1) / threads;
        init_kernel<<<blocks, threads>>>(out, b, total);
    }
    // K2: edge scatter
    {
        int threads = 256;
        long long work = (long long)E * 16;
        int blocks = (int)((work + threads - 1) / threads);
        scatter_kernel<<<blocks, threads>>>(ei, Wt, out, E);
    }
    // K3: log_softmax per row
    {
        int threads = 256;                 // 8 warps/block
        int blocks = (N + 7) / 8;
        softmax_kernel<<<blocks, threads>>>(out, N);
    }
}

// round 4
// speedup vs baseline: 1.6014x; 1.5907x over previous
#include <cuda_runtime.h>
#include <cuda_bf16.h>

// logits[i] = sum_{(i,j) in E} Wt[j] + b ; out = log_softmax(logits, axis=1)
// N=100000, E=3200000, C=64. edge_index int32 [2,E] (JAX x64-disabled).
//
// R4 strategy: build CSR per call (histogram -> scan -> position scatter),
// then a single fused pull kernel (one warp per row): register accumulation
// of gathered Wt rows + bias + log_softmax, single write. Removes the 819MB
// atomic-RMW stream and two auxiliary kernels vs the push version.

#define C 64
#define MAX_N 100000
#define MAX_E 3200000
#define SCAN_BLOCK 1024
#define MAX_SCAN_BLOCKS 128   // ceil(MAX_N / SCAN_BLOCK) = 98

__device__ int g_counts[MAX_N + 1];
__device__ int g_rowptr[MAX_N + 1];
__device__ int g_cursor[MAX_N + 1];
__device__ int g_blocksums[MAX_SCAN_BLOCKS];
__device__ int g_scol[MAX_E];

// ---------------- CSR build ----------------

__global__ void zero_counts_kernel(int N) {
    int i = blockIdx.x * blockDim.x + threadIdx.x;
    if (i <= N) g_counts[i] = 0;
}

__global__ void hist_kernel(const int* __restrict__ ei, int E) {
    int i = blockIdx.x * blockDim.x + threadIdx.x;
    if (i < E) atomicAdd(&g_counts[ei[i]], 1);
}

// Per-block exclusive scan of g_counts -> g_rowptr (local), block totals -> g_blocksums
__global__ void scan1_kernel(int N) {
    __shared__ int wsum[32];
    int t = threadIdx.x;
    int i = blockIdx.x * SCAN_BLOCK + t;
    int lane = t & 31, w = t >> 5;

    int val = (i < N) ? g_counts[i] : 0;

    // warp inclusive scan
    int x = val;
    #pragma unroll
    for (int off = 1; off < 32; off <<= 1) {
        int y = __shfl_up_sync(0xffffffffu, x, off);
        if (lane >= off) x += y;
    }
    if (lane == 31) wsum[w] = x;
    __syncthreads();

    // scan warp sums (warp 0)
    if (w == 0) {
        int s = wsum[lane];
        #pragma unroll
        for (int off = 1; off < 32; off <<= 1) {
            int y = __shfl_up_sync(0xffffffffu, s, off);
            if (lane >= off) s += y;
        }
        wsum[lane] = s;
    }
    __syncthreads();

    int warp_excl = (w == 0) ? 0 : wsum[w - 1];
    int excl = warp_excl + x - val;   // exclusive within block
    if (i < N) g_rowptr[i] = excl;
    if (t == SCAN_BLOCK - 1) g_blocksums[blockIdx.x] = warp_excl + x;
}

// Exclusive scan of block sums (single block)
__global__ void scan2_kernel(int nblocks) {
    __shared__ int sh[MAX_SCAN_BLOCKS];
    int t = threadIdx.x;
    if (t < nblocks) sh[t] = g_blocksums[t];
    __syncthreads();
    if (t == 0) {
        int acc = 0;
        for (int k = 0; k < nblocks; k++) {
            int v = sh[k];
            sh[k] = acc;
            acc += v;
        }
    }
    __syncthreads();
    if (t < nblocks) g_blocksums[t] = sh[t];
}

// Add block offsets; init cursors; set rowptr[N] = E
__global__ void scan3_kernel(int N, int E) {
    int i = blockIdx.x * blockDim.x + threadIdx.x;
    if (i < N) {
        int v = g_rowptr[i] + g_blocksums[blockIdx.x * blockDim.x >= 0 ? (i / SCAN_BLOCK) : 0];
        g_rowptr[i] = v;
        g_cursor[i] = v;
    }
    if (i == 0) g_rowptr[N] = E;
}

// Scatter cols into row-grouped order
__global__ void build_scol_kernel(const int* __restrict__ ei, int E) {
    int e = blockIdx.x * blockDim.x + threadIdx.x;
    if (e < E) {
        int row = ei[e];
        int col = ei[E + e];
        int pos = atomicAdd(&g_cursor[row], 1);
        g_scol[pos] = col;
    }
}

// ---------------- fused pull + bias + log_softmax ----------------

__global__ void pull_kernel(const float* __restrict__ Wt,
                            const float* __restrict__ b,
                            float* __restrict__ out,
                            int N) {
    int warp = (blockIdx.x * blockDim.x + threadIdx.x) >> 5;
    int lane = threadIdx.x & 31;
    if (warp >= N) return;

    int start = g_rowptr[warp];
    int end   = g_rowptr[warp + 1];

    const float2* bb = reinterpret_cast<const float2*>(b);
    float2 acc = __ldg(&bb[lane]);     // cols [2*lane, 2*lane+1]

    int j = start;
    for (; j + 4 <= end; j += 4) {
        int c0 = __ldg(&g_scol[j]);
        int c1 = __ldg(&g_scol[j + 1]);
        int c2 = __ldg(&g_scol[j + 2]);
        int c3 = __ldg(&g_scol[j + 3]);
        float2 v0 = __ldg(reinterpret_cast<const float2*>(Wt + (size_t)c0 * C) + lane);
        float2 v1 = __ldg(reinterpret_cast<const float2*>(Wt + (size_t)c1 * C) + lane);
        float2 v2 = __ldg(reinterpret_cast<const float2*>(Wt + (size_t)c2 * C) + lane);
        float2 v3 = __ldg(reinterpret_cast<const float2*>(Wt + (size_t)c3 * C) + lane);
        acc.x += (v0.x + v1.x) + (v2.x + v3.x);
        acc.y += (v0.y + v1.y) + (v2.y + v3.y);
    }
    for (; j < end; j++) {
        int c = __ldg(&g_scol[j]);
        float2 v = __ldg(reinterpret_cast<const float2*>(Wt + (size_t)c * C) + lane);
        acc.x += v.x;
        acc.y += v.y;
    }

    // log_softmax over the 64 values held as 32 x float2
    float m = fmaxf(acc.x, acc.y);
    #pragma unroll
    for (int off = 16; off > 0; off >>= 1)
        m = fmaxf(m, __shfl_xor_sync(0xffffffffu, m, off));

    float s = __expf(acc.x - m) + __expf(acc.y - m);
    #pragma unroll
    for (int off = 16; off > 0; off >>= 1)
        s += __shfl_xor_sync(0xffffffffu, s, off);

    float lse = m + logf(s);
    float2 o = make_float2(acc.x - lse, acc.y - lse);
    reinterpret_cast<float2*>(out + (size_t)warp * C)[lane] = o;
}

// ---------------- fallback (push w/ atomics) for unexpected sizes ----------------

__global__ void init_kernel(float* __restrict__ out, const float* __restrict__ b, int total) {
    int i = blockIdx.x * blockDim.x + threadIdx.x;
    if (i < total) out[i] = __ldg(&b[i & (C - 1)]);
}

__global__ void scatter_kernel(const int* __restrict__ ei, const float* __restrict__ Wt,
                               float* __restrict__ out, int E) {
    int gtid = blockIdx.x * blockDim.x + threadIdx.x;
    int e = gtid >> 4;
    int lane = threadIdx.x & 15;
    if (e >= E) return;
    int row = __ldg(&ei[e]);
    int col = __ldg(&ei[E + e]);
    const float4* src = reinterpret_cast<const float4*>(Wt + (long long)col * C);
    float4 v = __ldg(&src[lane]);
    float* dst = out + (long long)row * C + lane * 4;
    asm volatile("red.global.add.v4.f32 [%0], {%1, %2, %3, %4};"
                 :: "l"(dst), "f"(v.x), "f"(v.y), "f"(v.z), "f"(v.w) : "memory");
}

__global__ void softmax_kernel(float* __restrict__ out, int N) {
    int warp = (blockIdx.x * blockDim.x + threadIdx.x) >> 5;
    int lane = threadIdx.x & 31;
    if (warp >= N) return;
    float* rowp = out + (long long)warp * C;
    float v0 = rowp[lane];
    float v1 = rowp[lane + 32];
    float m = fmaxf(v0, v1);
    #pragma unroll
    for (int off = 16; off > 0; off >>= 1)
        m = fmaxf(m, __shfl_xor_sync(0xffffffffu, m, off));
    float s = __expf(v0 - m) + __expf(v1 - m);
    #pragma unroll
    for (int off = 16; off > 0; off >>= 1)
        s += __shfl_xor_sync(0xffffffffu, s, off);
    float lse = m + logf(s);
    rowp[lane]      = v0 - lse;
    rowp[lane + 32] = v1 - lse;
}

// ---------------- launch ----------------

extern "C" void kernel_launch(void* const* d_in, const int* in_sizes, int n_in,
                              void* d_out, int out_size) {
    const int*   ei = (const int*)d_in[0];   // [2, E] int32
    const float* Wt = (const float*)d_in[1]; // [N, C]
    const float* b  = (const float*)d_in[2]; // [C]
    float* out = (float*)d_out;              // [N, C]

    int E = in_sizes[0] / 2;
    int N = in_sizes[1] / C;

    if (N <= MAX_N && E <= MAX_E) {
        int nblocks_scan = (N + SCAN_BLOCK - 1) / SCAN_BLOCK;

        zero_counts_kernel<<<(N + 256) / 256, 256>>>(N);
        hist_kernel<<<(E + 255) / 256, 256>>>(ei, E);
        scan1_kernel<<<nblocks_scan, SCAN_BLOCK>>>(N);
        scan2_kernel<<<1, MAX_SCAN_BLOCKS>>>(nblocks_scan);
        scan3_kernel<<<nblocks_scan, SCAN_BLOCK>>>(N, E);
        build_scol_kernel<<<(E + 255) / 256, 256>>>(ei, E);

        int threads = 256; // 8 warps per block
        int blocks = (N + 7) / 8;
        pull_kernel<<<blocks, threads>>>(Wt, b, out, N);
    } else {
        int total = N * C;
        init_kernel<<<(total + 255) / 256, 256>>>(out, b, total);
        long long work = (long long)E * 16;
        scatter_kernel<<<(int)((work + 255) / 256), 256>>>(ei, Wt, out, E);
        softmax_kernel<<<(N + 7) / 8, 256>>>(out, N);
    }
}